// round 10
// baseline (speedup 1.0000x reference)
#include <cuda_runtime.h>
#include <cuda_bf16.h>
#include <cstdint>

#define VQ_D   64
#define VQ_M   512
#define TM     128                 // rows per main CTA
#define TNQ    128                 // codes per main CTA (quarter of 512)

#define WSTR       72              // smem row stride in bf16 (144 B) -> conflict-free ldmatrix
#define SPLIT_B    (128 * 144)     // one split tile: 128 rows x 144 B = 18432
#define SM_SEE     0               // 128 f32
#define SM_XX      512             // 128 f32
#define SM_A       1024            // 3 x 18432
#define SM_B       (SM_A + 3 * SPLIT_B)       // 56320
#define SMEM_BYTES (SM_B + 3 * SPLIT_B)       // 111616

#define MARGIN 4e-5f               // hmma->exact rescore window (>> 2*hmma error, ~5 ulp buckets)

__device__ float              g_ee[VQ_M];
__device__ int                g_cnt[VQ_M];
__device__ unsigned long long g_keys[131072];
__device__ unsigned short     g_esplit[3 * VQ_M * VQ_D];   // bf16 splits of e, [split][code][k]
__device__ double             g_part[512];

__device__ __forceinline__ unsigned int ford(float f) {
    unsigned int u = __float_as_uint(f);
    return (u & 0x80000000u) ? ~u : (u | 0x80000000u);
}

__device__ __forceinline__ uint32_t smem_u32(const void* p) {
    uint32_t a;
    asm("{ .reg .u64 t; cvta.to.shared.u64 t, %1; cvt.u32.u64 %0, t; }" : "=r"(a) : "l"(p));
    return a;
}

__device__ __forceinline__ void split3(float v, unsigned short& s1,
                                       unsigned short& s2, unsigned short& s3) {
    __nv_bfloat16 h1 = __float2bfloat16_rn(v);
    float r1 = v - __bfloat162float(h1);          // exact
    __nv_bfloat16 h2 = __float2bfloat16_rn(r1);
    float r2 = r1 - __bfloat162float(h2);         // exact
    __nv_bfloat16 h3 = __float2bfloat16_rn(r2);   // v ~= h1+h2+h3 (error < 2^-27 rel)
    s1 = __bfloat16_as_ushort(h1);
    s2 = __bfloat16_as_ushort(h2);
    s3 = __bfloat16_as_ushort(h3);
}

__device__ __forceinline__ void ldsm_x4(uint32_t* r, uint32_t addr) {
    asm volatile("ldmatrix.sync.aligned.m8n8.x4.shared.b16 {%0,%1,%2,%3}, [%4];"
                 : "=r"(r[0]), "=r"(r[1]), "=r"(r[2]), "=r"(r[3]) : "r"(addr));
}

__device__ __forceinline__ void mma_bf16(float* c, const uint32_t* a, uint32_t b0, uint32_t b1) {
    asm volatile("mma.sync.aligned.m16n8k16.row.col.f32.bf16.bf16.f32 "
                 "{%0,%1,%2,%3}, {%4,%5,%6,%7}, {%8,%9}, {%0,%1,%2,%3};"
                 : "+f"(c[0]), "+f"(c[1]), "+f"(c[2]), "+f"(c[3])
                 : "r"(a[0]), "r"(a[1]), "r"(a[2]), "r"(a[3]), "r"(b0), "r"(b1));
}

// Exact rescore: reference-matching rounding (sequential fmaf over k, fl(fl(xx-2p)+ee)).
// __noinline__ keeps the rare path a real branch (no if-conversion of 64 fmaf + 32 LDG).
__device__ __noinline__ unsigned long long vq_rescore(
    const float* __restrict__ xr, const float* __restrict__ er,
    float xxv, float eev, int gcode)
{
    float p = 0.f;
    const float4* xa = (const float4*)xr;
    const float4* eb = (const float4*)er;
    #pragma unroll
    for (int q = 0; q < VQ_D / 4; ++q) {
        float4 a = __ldg(xa + q);
        float4 b = __ldg(eb + q);
        p = fmaf(a.x, b.x, p);
        p = fmaf(a.y, b.y, p);
        p = fmaf(a.z, b.z, p);
        p = fmaf(a.w, b.w, p);
    }
    float d = (xxv - 2.0f * p) + eev;
    return ((unsigned long long)ford(d) << 32) | (unsigned int)gcode;
}

// ---------------- prep: reset keys/cnt, ee, 3-way bf16 split of e ----------------
__global__ void vq_prep(const float* __restrict__ emb, int nRows) {
    int b = blockIdx.x, t = threadIdx.x;
    int gid = b * 256 + t;
    if (gid < nRows) g_keys[gid] = ~0ull;

    if (b < 128) {                                   // 128*256 = 32768 = 512*64 elements
        int eidx = b * 256 + t;
        unsigned short s1, s2, s3;
        split3(emb[eidx], s1, s2, s3);
        g_esplit[0 * 32768 + eidx] = s1;
        g_esplit[1 * 32768 + eidx] = s2;
        g_esplit[2 * 32768 + eidx] = s3;
    } else if (b < 130) {                            // 512 codes: cnt reset + ||e||^2
        int code = (b - 128) * 256 + t;
        g_cnt[code] = 0;
        const float* e = emb + code * VQ_D;
        float s = 0.f;
        #pragma unroll
        for (int k = 0; k < VQ_D; ++k) s = fmaf(e[k], e[k], s);
        g_ee[code] = s;
    }
}

// ---------------- main: split-bf16 mma.sync GEMM + exact-rescored argmin ----------------
__global__ __launch_bounds__(256, 2) void vq_main(
    const float* __restrict__ x, const float* __restrict__ emb, int nRows)
{
    extern __shared__ char smem[];
    float* see = (float*)(smem + SM_SEE);
    float* xxs = (float*)(smem + SM_XX);

    const int tid  = threadIdx.x;
    const int lane = tid & 31;
    const int wid  = tid >> 5;
    const int tile = blockIdx.x >> 2;
    const int q    = blockIdx.x & 3;
    const int row0 = tile * TM;
    const int col0 = q * TNQ;

    // ---- stage ||e||^2 for this quarter
    if (tid < TNQ) see[tid] = g_ee[col0 + tid];

    // ---- B tiles: copy pre-split e rows (128 codes x 64 bf16 per split) into padded smem
    {
        int c = tid >> 1, h = tid & 1;               // each thread: 32 bf16 = 64 bytes
        #pragma unroll
        for (int s = 0; s < 3; ++s) {
            const uint4* src = (const uint4*)&g_esplit[s * 32768 + (col0 + c) * VQ_D + h * 32];
            char* dst = smem + SM_B + s * SPLIT_B + c * 144 + h * 64;
            *(uint4*)(dst)      = __ldg(src);
            *(uint4*)(dst + 16) = __ldg(src + 1);
            *(uint4*)(dst + 32) = __ldg(src + 2);
            *(uint4*)(dst + 48) = __ldg(src + 3);
        }
    }

    // ---- A tiles: load x rows, 3-way bf16 split, store padded K-major
    {
        int r = tid >> 1, h = tid & 1;
        const float4* xp = (const float4*)(x + (size_t)(row0 + r) * VQ_D + h * 32);
        char* abase = smem + SM_A + r * 144 + h * 64;
        #pragma unroll
        for (int j = 0; j < 8; ++j) {
            float4 v = __ldg(xp + j);
            unsigned short a1[4], a2[4], a3[4];
            split3(v.x, a1[0], a2[0], a3[0]);
            split3(v.y, a1[1], a2[1], a3[1]);
            split3(v.z, a1[2], a2[2], a3[2]);
            split3(v.w, a1[3], a2[3], a3[3]);
            *(uint2*)(abase + 0 * SPLIT_B + j * 8) =
                make_uint2((uint32_t)a1[0] | ((uint32_t)a1[1] << 16),
                           (uint32_t)a1[2] | ((uint32_t)a1[3] << 16));
            *(uint2*)(abase + 1 * SPLIT_B + j * 8) =
                make_uint2((uint32_t)a2[0] | ((uint32_t)a2[1] << 16),
                           (uint32_t)a2[2] | ((uint32_t)a2[3] << 16));
            *(uint2*)(abase + 2 * SPLIT_B + j * 8) =
                make_uint2((uint32_t)a3[0] | ((uint32_t)a3[1] << 16),
                           (uint32_t)a3[2] | ((uint32_t)a3[3] << 16));
        }
    }

    // ---- xx per row (sequential fmaf: reference-matched form)
    if (tid < TM) {
        const float* xr = x + (size_t)(row0 + tid) * VQ_D;
        float s = 0.f;
        #pragma unroll
        for (int k = 0; k < VQ_D; ++k) s = fmaf(xr[k], xr[k], s);
        xxs[tid] = s;
    }
    __syncthreads();

    // ---- warp tiles: 4m x 2n grid, warp tile 32 rows x 64 codes
    const int wm = wid >> 1;
    const int wn = wid & 1;

    float acc[2][8][4];
    #pragma unroll
    for (int mi = 0; mi < 2; ++mi)
        #pragma unroll
        for (int ni = 0; ni < 8; ++ni)
            #pragma unroll
            for (int v = 0; v < 4; ++v) acc[mi][ni][v] = 0.f;

    const uint32_t sbase = smem_u32(smem);
    const uint32_t aBase = sbase + SM_A +
        (uint32_t)(((wm * 32 + (lane & 15)) * WSTR + (lane >> 4) * 8) * 2);
    const uint32_t bBase = sbase + SM_B +
        (uint32_t)(((wn * 64 + (lane & 7) + ((lane >> 4) * 8)) * WSTR + ((lane >> 3) & 1) * 8) * 2);

    const int pa[6] = {0, 0, 1, 1, 2, 0};
    const int pb[6] = {0, 1, 0, 1, 0, 2};
    #pragma unroll
    for (int p = 0; p < 6; ++p) {
        uint32_t aS = aBase + pa[p] * SPLIT_B;
        uint32_t bS = bBase + pb[p] * SPLIT_B;
        #pragma unroll
        for (int ks = 0; ks < 4; ++ks) {
            uint32_t a0[4], a1[4];
            ldsm_x4(a0, aS + ks * 32);
            ldsm_x4(a1, aS + 16 * 144 + ks * 32);
            uint32_t bb[4][4];
            #pragma unroll
            for (int nb = 0; nb < 4; ++nb)
                ldsm_x4(bb[nb], bS + nb * 16 * 144 + ks * 32);
            #pragma unroll
            for (int ni = 0; ni < 8; ++ni) {
                uint32_t b0 = bb[ni >> 1][(ni & 1) * 2];
                uint32_t b1 = bb[ni >> 1][(ni & 1) * 2 + 1];
                mma_bf16(acc[0][ni], a0, b0, b1);
                mma_bf16(acc[1][ni], a1, b0, b1);
            }
        }
    }

    // ---- epilogue: hmma prune -> exact rescore of margin candidates -> exact-key argmin
    #pragma unroll
    for (int mi = 0; mi < 2; ++mi) {
        #pragma unroll
        for (int rh = 0; rh < 2; ++rh) {
            int rowl = wm * 32 + mi * 16 + rh * 8 + (lane >> 2);
            float xxv = xxs[rowl];
            float dv[16];
            float gmin = __int_as_float(0x7f800000);
            #pragma unroll
            for (int ni = 0; ni < 8; ++ni) {
                #pragma unroll
                for (int sub = 0; sub < 2; ++sub) {
                    float p = acc[mi][ni][rh * 2 + sub];
                    int col = wn * 64 + ni * 8 + (lane & 3) * 2 + sub;
                    float d = (xxv - 2.0f * p) + see[col];
                    dv[ni * 2 + sub] = d;
                    gmin = fminf(gmin, d);
                }
            }
            // group (row x 64-code) hmma min across the quad
            gmin = fminf(gmin, __shfl_xor_sync(0xffffffffu, gmin, 1));
            gmin = fminf(gmin, __shfl_xor_sync(0xffffffffu, gmin, 2));
            float thr = gmin + MARGIN;

            unsigned long long best = ~0ull;
            const float* xr = x + (size_t)(row0 + rowl) * VQ_D;
            #pragma unroll
            for (int t2 = 0; t2 < 16; ++t2) {
                if (dv[t2] <= thr) {
                    int col = wn * 64 + (t2 >> 1) * 8 + (lane & 3) * 2 + (t2 & 1);
                    int gcode = col0 + col;
                    unsigned long long key =
                        vq_rescore(xr, emb + (size_t)gcode * VQ_D, xxv, see[col], gcode);
                    if (key < best) best = key;
                }
            }
            unsigned long long o = __shfl_xor_sync(0xffffffffu, best, 1);
            if (o < best) best = o;
            o = __shfl_xor_sync(0xffffffffu, best, 2);
            if (o < best) best = o;
            if ((lane & 3) == 0) atomicMin(&g_keys[row0 + rowl], best);
        }
    }
}

// ---------------- post: gather + straight-through output + loss partials + counts ----------------
__global__ __launch_bounds__(256) void vq_post(
    const float* __restrict__ x, const float* __restrict__ emb,
    float* __restrict__ out, int nRows)
{
    __shared__ double lred[8];
    const int t = threadIdx.x, b = blockIdx.x;
    const int lane = t & 31;
    double ls = 0.0;
    #pragma unroll
    for (int i = 0; i < 4; ++i) {
        int rl = i * 64 + (t >> 2);
        int grow = b * 256 + rl;
        int q4 = t & 3;
        int idx = (int)(g_keys[grow] & 0xffffffffull);
        if (q4 == 0) atomicAdd(&g_cnt[idx], 1);
        const float4* x4 = (const float4*)x;
        const float4* e4 = (const float4*)emb;
        float4* o4 = (float4*)out;
        #pragma unroll
        for (int j = 0; j < 4; ++j) {
            int fo = grow * (VQ_D / 4) + q4 * 4 + j;
            float4 xa = x4[fo];
            float4 ea = e4[idx * (VQ_D / 4) + q4 * 4 + j];
            float4 st;
            st.x = xa.x + (ea.x - xa.x);
            st.y = xa.y + (ea.y - xa.y);
            st.z = xa.z + (ea.z - xa.z);
            st.w = xa.w + (ea.w - xa.w);
            o4[fo] = st;
            float d0 = xa.x - ea.x, d1 = xa.y - ea.y;
            float d2 = xa.z - ea.z, d3 = xa.w - ea.w;
            ls += (double)(d0 * d0) + (double)(d1 * d1) + (double)(d2 * d2) + (double)(d3 * d3);
        }
    }
    #pragma unroll
    for (int m = 16; m > 0; m >>= 1) ls += __shfl_xor_sync(0xffffffffu, ls, m);
    if (lane == 0) lred[t >> 5] = ls;
    __syncthreads();
    if (t < 32) {
        double s = (t < 8) ? lred[t] : 0.0;
        #pragma unroll
        for (int m = 4; m > 0; m >>= 1) s += __shfl_xor_sync(0xffffffffu, s, m);
        if (t == 0) g_part[b] = s;
    }
}

__global__ __launch_bounds__(512) void vq_final(float* __restrict__ out, int nElems,
                                                int nBlocks, float invRows)
{
    __shared__ double sd[512];
    int t = threadIdx.x;
    double s = 0.0;
    for (int b2 = t; b2 < nBlocks; b2 += 512) s += g_part[b2];   // fixed order -> deterministic
    sd[t] = s; __syncthreads();
    for (int h = 256; h > 0; h >>= 1) { if (t < h) sd[t] += sd[t + h]; __syncthreads(); }
    double lossSum = sd[0];
    __syncthreads();

    float p = (float)g_cnt[t] * invRows;            // exact: invRows is a power of 2
    float term = p * logf(p + 1e-10f);
    sd[t] = (double)term; __syncthreads();
    for (int h = 256; h > 0; h >>= 1) { if (t < h) sd[t] += sd[t + h]; __syncthreads(); }

    if (t == 0) {
        float mean = (float)(lossSum / (double)nElems);
        out[nElems]     = 0.25f * mean;             // commitment loss
        out[nElems + 1] = expf(-(float)sd[0]);      // perplexity
    }
}

extern "C" void kernel_launch(void* const* d_in, const int* in_sizes, int n_in,
                              void* d_out, int out_size)
{
    const float* x   = (const float*)d_in[0];
    const float* emb = (const float*)d_in[1];
    int nElems = in_sizes[0];
    if (n_in >= 2 && in_sizes[0] < in_sizes[1]) {   // defensive: x is the big tensor
        x = (const float*)d_in[1];
        emb = (const float*)d_in[0];
        nElems = in_sizes[1];
    }
    float* out = (float*)d_out;
    int nRows     = nElems / VQ_D;                  // 131072
    int nPrepBlks = nRows / 256;                    // 512 (covers keys reset + splits + ee)
    int nMainBlks = (nRows / TM) * 4;               // 4096
    int nPostBlks = nRows / 256;                    // 512

    cudaFuncSetAttribute(vq_main, cudaFuncAttributeMaxDynamicSharedMemorySize, SMEM_BYTES);

    vq_prep<<<nPrepBlks, 256>>>(emb, nRows);
    vq_main<<<nMainBlks, 256, SMEM_BYTES>>>(x, emb, nRows);
    vq_post<<<nPostBlks, 256>>>(x, emb, out, nRows);
    vq_final<<<1, 512>>>(out, nElems, nPostBlks, 1.0f / (float)nRows);
}

// round 11
// speedup vs baseline: 2.2591x; 2.2591x over previous
#include <cuda_runtime.h>
#include <cuda_bf16.h>
#include <cstdint>

#define VQ_D   64
#define VQ_M   512
#define TM     128                 // rows per main CTA
#define TNH    256                 // codes per main CTA (half of 512)

#define WSTR     72                // smem row stride in bf16 (144 B) -> conflict-free ldmatrix
#define SPLIT_A  (128 * 144)       // 18432
#define SPLIT_B  (256 * 144)       // 36864
#define SM_SEE   0                 // 256 f32 = 1024
#define SM_XX    1024              // 128 f32 = 512
#define SM_GK    1536              // 128*4 f32 group mins = 2048
#define SM_GC    3584              // 128*4 u16 group argmin cols = 1024
#define SM_A     4608              // 2 splits x 18432 = 36864
#define SM_B     (SM_A + 2 * SPLIT_A)        // 41472
#define SMEM_BYTES (SM_B + 2 * SPLIT_B)      // 115200  (2 CTAs/SM incl. 1KB reserve)

#define MARGIN 4e-5f               // hmma->exact window (~5 ulp of d~64; 2*delta needs < 2 ulp)

__device__ float              g_ee[VQ_M];
__device__ int                g_cnt[VQ_M];
__device__ unsigned long long g_keys[131072];
__device__ unsigned short     g_esplit[2 * VQ_M * VQ_D];   // 2-way bf16 splits of e
__device__ double             g_part[512];

__device__ __forceinline__ unsigned int ford(float f) {
    unsigned int u = __float_as_uint(f);
    return (u & 0x80000000u) ? ~u : (u | 0x80000000u);
}

__device__ __forceinline__ uint32_t smem_u32(const void* p) {
    uint32_t a;
    asm("{ .reg .u64 t; cvta.to.shared.u64 t, %1; cvt.u32.u64 %0, t; }" : "=r"(a) : "l"(p));
    return a;
}

__device__ __forceinline__ void split2(float v, unsigned short& s1, unsigned short& s2) {
    __nv_bfloat16 h1 = __float2bfloat16_rn(v);
    float r1 = v - __bfloat162float(h1);          // exact
    __nv_bfloat16 h2 = __float2bfloat16_rn(r1);   // v = h1+h2 + O(2^-17 v)
    s1 = __bfloat16_as_ushort(h1);
    s2 = __bfloat16_as_ushort(h2);
}

__device__ __forceinline__ void ldsm_x4(uint32_t* r, uint32_t addr) {
    asm volatile("ldmatrix.sync.aligned.m8n8.x4.shared.b16 {%0,%1,%2,%3}, [%4];"
                 : "=r"(r[0]), "=r"(r[1]), "=r"(r[2]), "=r"(r[3]) : "r"(addr));
}

__device__ __forceinline__ void mma_bf16(float* c, const uint32_t* a, uint32_t b0, uint32_t b1) {
    asm volatile("mma.sync.aligned.m16n8k16.row.col.f32.bf16.bf16.f32 "
                 "{%0,%1,%2,%3}, {%4,%5,%6,%7}, {%8,%9}, {%0,%1,%2,%3};"
                 : "+f"(c[0]), "+f"(c[1]), "+f"(c[2]), "+f"(c[3])
                 : "r"(a[0]), "r"(a[1]), "r"(a[2]), "r"(a[3]), "r"(b0), "r"(b1));
}

// Exact rescore with reference-matching rounding (sequential fmaf, fl(fl(xx-2p)+ee)).
// __noinline__ keeps the (rare) call sites from bloating the hot loops.
__device__ __noinline__ unsigned long long vq_exact_key(
    const float* __restrict__ xr, const float* __restrict__ er,
    float xxv, float eev, int gcode)
{
    float p = 0.f;
    const float4* xa = (const float4*)xr;
    const float4* eb = (const float4*)er;
    #pragma unroll
    for (int q = 0; q < VQ_D / 4; ++q) {
        float4 a = __ldg(xa + q);
        float4 b = __ldg(eb + q);
        p = fmaf(a.x, b.x, p);
        p = fmaf(a.y, b.y, p);
        p = fmaf(a.z, b.z, p);
        p = fmaf(a.w, b.w, p);
    }
    float d = (xxv - 2.0f * p) + eev;
    return ((unsigned long long)ford(d) << 32) | (unsigned int)gcode;
}

// ---------------- prep: reset keys/cnt, ee, 2-way bf16 split of e ----------------
__global__ void vq_prep(const float* __restrict__ emb, int nRows) {
    int b = blockIdx.x, t = threadIdx.x;
    int gid = b * 256 + t;
    if (gid < nRows) g_keys[gid] = ~0ull;

    if (b < 128) {                                   // 32768 = 512*64 elements
        int eidx = b * 256 + t;
        unsigned short s1, s2;
        split2(emb[eidx], s1, s2);
        g_esplit[0 * 32768 + eidx] = s1;
        g_esplit[1 * 32768 + eidx] = s2;
    } else if (b < 130) {
        int code = (b - 128) * 256 + t;
        g_cnt[code] = 0;
        const float* e = emb + code * VQ_D;
        float s = 0.f;
        #pragma unroll
        for (int k = 0; k < VQ_D; ++k) s = fmaf(e[k], e[k], s);
        g_ee[code] = s;
    }
}

// ---------------- main: 3-term split-bf16 GEMM + deferred exact-rescored argmin ----------------
__global__ __launch_bounds__(256, 2) void vq_main(
    const float* __restrict__ x, const float* __restrict__ emb, int nRows)
{
    extern __shared__ char smem[];
    float*          see = (float*)(smem + SM_SEE);
    float*          xxs = (float*)(smem + SM_XX);
    float*          gk  = (float*)(smem + SM_GK);
    unsigned short* gc  = (unsigned short*)(smem + SM_GC);

    const int tid  = threadIdx.x;
    const int lane = tid & 31;
    const int wid  = tid >> 5;
    const int tile = blockIdx.x >> 1;
    const int half = blockIdx.x & 1;
    const int row0 = tile * TM;
    const int col0 = half * TNH;

    // ---- stage ||e||^2 for this half
    see[tid] = g_ee[col0 + tid];

    // ---- B tiles: copy pre-split e rows (256 codes x 64 bf16 x 2 splits) into padded smem
    {
        int c2 = tid >> 1, h = tid & 1;              // 32 bf16 = 64 B per unit
        #pragma unroll
        for (int it = 0; it < 2; ++it) {
            int c = it * 128 + c2;
            #pragma unroll
            for (int s = 0; s < 2; ++s) {
                const uint4* src = (const uint4*)&g_esplit[s * 32768 + (col0 + c) * VQ_D + h * 32];
                char* dst = smem + SM_B + s * SPLIT_B + c * 144 + h * 64;
                *(uint4*)(dst)      = __ldg(src);
                *(uint4*)(dst + 16) = __ldg(src + 1);
                *(uint4*)(dst + 32) = __ldg(src + 2);
                *(uint4*)(dst + 48) = __ldg(src + 3);
            }
        }
    }

    // ---- A tiles: load x rows, 2-way bf16 split, store padded K-major
    {
        int r = tid >> 1, h = tid & 1;
        const float4* xp = (const float4*)(x + (size_t)(row0 + r) * VQ_D + h * 32);
        char* abase = smem + SM_A + r * 144 + h * 64;
        #pragma unroll
        for (int j = 0; j < 8; ++j) {
            float4 v = __ldg(xp + j);
            unsigned short a1[4], a2[4];
            split2(v.x, a1[0], a2[0]);
            split2(v.y, a1[1], a2[1]);
            split2(v.z, a1[2], a2[2]);
            split2(v.w, a1[3], a2[3]);
            *(uint2*)(abase + 0 * SPLIT_A + j * 8) =
                make_uint2((uint32_t)a1[0] | ((uint32_t)a1[1] << 16),
                           (uint32_t)a1[2] | ((uint32_t)a1[3] << 16));
            *(uint2*)(abase + 1 * SPLIT_A + j * 8) =
                make_uint2((uint32_t)a2[0] | ((uint32_t)a2[1] << 16),
                           (uint32_t)a2[2] | ((uint32_t)a2[3] << 16));
        }
    }

    // ---- xx per row (sequential fmaf: reference-matched form)
    if (tid < TM) {
        const float* xr = x + (size_t)(row0 + tid) * VQ_D;
        float s = 0.f;
        #pragma unroll
        for (int k = 0; k < VQ_D; ++k) s = fmaf(xr[k], xr[k], s);
        xxs[tid] = s;
    }
    __syncthreads();

    // ---- 8 warps as 4m x 2n; warp tile 32 rows x 64 codes; 2 n-iterations cover 256 codes
    const int wm = wid >> 1;
    const int wn = wid & 1;
    const uint32_t sbase = smem_u32(smem);
    const uint32_t aBase = sbase + SM_A +
        (uint32_t)(((wm * 32 + (lane & 15)) * WSTR + (lane >> 4) * 8) * 2);

    const int pa[3] = {0, 0, 1};
    const int pb[3] = {0, 1, 0};

    #pragma unroll
    for (int wn2 = 0; wn2 < 2; ++wn2) {
        float acc[2][8][4];
        #pragma unroll
        for (int mi = 0; mi < 2; ++mi)
            #pragma unroll
            for (int ni = 0; ni < 8; ++ni)
                #pragma unroll
                for (int v = 0; v < 4; ++v) acc[mi][ni][v] = 0.f;

        const uint32_t bBase = sbase + SM_B +
            (uint32_t)(((wn2 * 128 + wn * 64 + (lane & 7) + ((lane >> 4) * 8)) * WSTR +
                        ((lane >> 3) & 1) * 8) * 2);

        #pragma unroll
        for (int p = 0; p < 3; ++p) {
            uint32_t aS = aBase + pa[p] * SPLIT_A;
            uint32_t bS = bBase + pb[p] * SPLIT_B;
            #pragma unroll
            for (int ks = 0; ks < 4; ++ks) {
                uint32_t a0[4], a1[4];
                ldsm_x4(a0, aS + ks * 32);
                ldsm_x4(a1, aS + 16 * 144 + ks * 32);
                uint32_t bb[4][4];
                #pragma unroll
                for (int nb = 0; nb < 4; ++nb)
                    ldsm_x4(bb[nb], bS + nb * 16 * 144 + ks * 32);
                #pragma unroll
                for (int ni = 0; ni < 8; ++ni) {
                    uint32_t b0 = bb[ni >> 1][(ni & 1) * 2];
                    uint32_t b1 = bb[ni >> 1][(ni & 1) * 2 + 1];
                    mma_bf16(acc[0][ni], a0, b0, b1);
                    mma_bf16(acc[1][ni], a1, b0, b1);
                }
            }
        }

        // ---- partial epilogue: per-group (row x 64 codes) hmma min -> smem; rare extras now
        #pragma unroll
        for (int mi = 0; mi < 2; ++mi) {
            #pragma unroll
            for (int rh = 0; rh < 2; ++rh) {
                int rowl = wm * 32 + mi * 16 + rh * 8 + (lane >> 2);
                float xxv = xxs[rowl];
                float dv[16];
                float lmin = __int_as_float(0x7f800000);
                int   lcol = 0x7fffffff;
                #pragma unroll
                for (int ni = 0; ni < 8; ++ni) {
                    #pragma unroll
                    for (int sub = 0; sub < 2; ++sub) {
                        int col = wn2 * 128 + wn * 64 + ni * 8 + (lane & 3) * 2 + sub;
                        float d = (xxv - 2.0f * acc[mi][ni][rh * 2 + sub]) + see[col];
                        dv[ni * 2 + sub] = d;
                        if (d < lmin || (d == lmin && col < lcol)) { lmin = d; lcol = col; }
                    }
                }
                #pragma unroll
                for (int m = 1; m <= 2; m <<= 1) {
                    float od = __shfl_xor_sync(0xffffffffu, lmin, m);
                    int   oc = __shfl_xor_sync(0xffffffffu, lcol, m);
                    if (od < lmin || (od == lmin && oc < lcol)) { lmin = od; lcol = oc; }
                }
                int g = wn2 * 2 + wn;
                if ((lane & 3) == 0) {
                    gk[rowl * 4 + g] = lmin;
                    gc[rowl * 4 + g] = (unsigned short)lcol;
                }
                // rare: extra in-group candidates within margin of the group min
                float thr = lmin + MARGIN;
                #pragma unroll
                for (int t2 = 0; t2 < 16; ++t2) {
                    if (dv[t2] <= thr) {
                        int col = wn2 * 128 + wn * 64 + (t2 >> 1) * 8 + (lane & 3) * 2 + (t2 & 1);
                        if (col != lcol) {
                            unsigned long long key = vq_exact_key(
                                x + (size_t)(row0 + rowl) * VQ_D,
                                emb + (size_t)(col0 + col) * VQ_D,
                                xxv, see[col], col0 + col);
                            atomicMin(&g_keys[row0 + rowl], key);
                        }
                    }
                }
            }
        }
    }
    __syncthreads();

    // ---- row owner: rescore only groups within margin of the CTA row min (~1.05/row)
    if (tid < TM) {
        float k0 = gk[tid * 4 + 0], k1 = gk[tid * 4 + 1];
        float k2 = gk[tid * 4 + 2], k3 = gk[tid * 4 + 3];
        float rowMin = fminf(fminf(k0, k1), fminf(k2, k3));
        float thr = rowMin + MARGIN;
        float xxv = xxs[tid];
        const float* xr = x + (size_t)(row0 + tid) * VQ_D;
        unsigned long long best = ~0ull;
        #pragma unroll
        for (int g = 0; g < 4; ++g) {
            if (gk[tid * 4 + g] <= thr) {
                int col = gc[tid * 4 + g];
                unsigned long long key = vq_exact_key(
                    xr, emb + (size_t)(col0 + col) * VQ_D, xxv, see[col], col0 + col);
                if (key < best) best = key;
            }
        }
        atomicMin(&g_keys[row0 + tid], best);
    }
}

// ---------------- post: gather + straight-through output + loss partials + counts ----------------
__global__ __launch_bounds__(256) void vq_post(
    const float* __restrict__ x, const float* __restrict__ emb,
    float* __restrict__ out, int nRows)
{
    __shared__ double lred[8];
    const int t = threadIdx.x, b = blockIdx.x;
    const int lane = t & 31;
    double ls = 0.0;
    #pragma unroll
    for (int i = 0; i < 4; ++i) {
        int rl = i * 64 + (t >> 2);
        int grow = b * 256 + rl;
        int q4 = t & 3;
        int idx = (int)(g_keys[grow] & 0xffffffffull);
        if (q4 == 0) atomicAdd(&g_cnt[idx], 1);
        const float4* x4 = (const float4*)x;
        const float4* e4 = (const float4*)emb;
        float4* o4 = (float4*)out;
        #pragma unroll
        for (int j = 0; j < 4; ++j) {
            int fo = grow * (VQ_D / 4) + q4 * 4 + j;
            float4 xa = x4[fo];
            float4 ea = e4[idx * (VQ_D / 4) + q4 * 4 + j];
            float4 st;
            st.x = xa.x + (ea.x - xa.x);
            st.y = xa.y + (ea.y - xa.y);
            st.z = xa.z + (ea.z - xa.z);
            st.w = xa.w + (ea.w - xa.w);
            o4[fo] = st;
            float d0 = xa.x - ea.x, d1 = xa.y - ea.y;
            float d2 = xa.z - ea.z, d3 = xa.w - ea.w;
            ls += (double)(d0 * d0) + (double)(d1 * d1) + (double)(d2 * d2) + (double)(d3 * d3);
        }
    }
    #pragma unroll
    for (int m = 16; m > 0; m >>= 1) ls += __shfl_xor_sync(0xffffffffu, ls, m);
    if (lane == 0) lred[t >> 5] = ls;
    __syncthreads();
    if (t < 32) {
        double s = (t < 8) ? lred[t] : 0.0;
        #pragma unroll
        for (int m = 4; m > 0; m >>= 1) s += __shfl_xor_sync(0xffffffffu, s, m);
        if (t == 0) g_part[b] = s;
    }
}

__global__ __launch_bounds__(512) void vq_final(float* __restrict__ out, int nElems,
                                                int nBlocks, float invRows)
{
    __shared__ double sd[512];
    int t = threadIdx.x;
    double s = 0.0;
    for (int b2 = t; b2 < nBlocks; b2 += 512) s += g_part[b2];   // fixed order -> deterministic
    sd[t] = s; __syncthreads();
    for (int h = 256; h > 0; h >>= 1) { if (t < h) sd[t] += sd[t + h]; __syncthreads(); }
    double lossSum = sd[0];
    __syncthreads();

    float p = (float)g_cnt[t] * invRows;            // exact: invRows is a power of 2
    float term = p * logf(p + 1e-10f);
    sd[t] = (double)term; __syncthreads();
    for (int h = 256; h > 0; h >>= 1) { if (t < h) sd[t] += sd[t + h]; __syncthreads(); }

    if (t == 0) {
        float mean = (float)(lossSum / (double)nElems);
        out[nElems]     = 0.25f * mean;             // commitment loss
        out[nElems + 1] = expf(-(float)sd[0]);      // perplexity
    }
}

extern "C" void kernel_launch(void* const* d_in, const int* in_sizes, int n_in,
                              void* d_out, int out_size)
{
    const float* x   = (const float*)d_in[0];
    const float* emb = (const float*)d_in[1];
    int nElems = in_sizes[0];
    if (n_in >= 2 && in_sizes[0] < in_sizes[1]) {   // defensive: x is the big tensor
        x = (const float*)d_in[1];
        emb = (const float*)d_in[0];
        nElems = in_sizes[1];
    }
    float* out = (float*)d_out;
    int nRows     = nElems / VQ_D;                  // 131072
    int nPrepBlks = nRows / 256;                    // 512
    int nMainBlks = (nRows / TM) * 2;               // 2048
    int nPostBlks = nRows / 256;                    // 512

    cudaFuncSetAttribute(vq_main, cudaFuncAttributeMaxDynamicSharedMemorySize, SMEM_BYTES);

    vq_prep<<<nPrepBlks, 256>>>(emb, nRows);
    vq_main<<<nMainBlks, 256, SMEM_BYTES>>>(x, emb, nRows);
    vq_post<<<nPostBlks, 256>>>(x, emb, out, nRows);
    vq_final<<<1, 512>>>(out, nElems, nPostBlks, 1.0f / (float)nRows);
}